// round 5
// baseline (speedup 1.0000x reference)
#include <cuda_runtime.h>

#define Bn 32
#define Cn 256
#define Tn 4096

// 8 MB scratch for per-batch energy/attention matrices (float4-aligned).
__device__ float4 g_attn4[(size_t)Bn * Cn * Cn / 4];

// ---------------------------------------------------------------------------
// Packed fp32x2 helpers (Blackwell FFMA2 — only reachable via PTX fma.rn.f32x2)
// ---------------------------------------------------------------------------
__device__ __forceinline__ unsigned long long pack2(float lo, float hi) {
    unsigned long long r;
    asm("mov.b64 %0, {%1, %2};" : "=l"(r) : "f"(lo), "f"(hi));
    return r;
}
__device__ __forceinline__ void ffma2(unsigned long long& d,
                                      unsigned long long a,
                                      unsigned long long b) {
    asm("fma.rn.f32x2 %0, %1, %2, %0;" : "+l"(d) : "l"(a), "l"(b));
}
__device__ __forceinline__ void unpack2(unsigned long long v, float& lo, float& hi) {
    asm("mov.b64 {%0, %1}, %2;" : "=f"(lo), "=f"(hi) : "l"(v));
}

// Store a 128x16 K-major tile transposed into smem [k][m] (stride 132 keeps
// float4 alignment on rows; 2-way store conflicts only, stores are issue-only).
__device__ __forceinline__ void store_tr(float (*dstA)[132], float (*dstB)[132],
                                         const float4* pa, const float4* pb,
                                         int kv, int m0, int m1) {
    dstA[kv * 4 + 0][m0] = pa[0].x; dstA[kv * 4 + 1][m0] = pa[0].y;
    dstA[kv * 4 + 2][m0] = pa[0].z; dstA[kv * 4 + 3][m0] = pa[0].w;
    dstA[kv * 4 + 0][m1] = pa[1].x; dstA[kv * 4 + 1][m1] = pa[1].y;
    dstA[kv * 4 + 2][m1] = pa[1].z; dstA[kv * 4 + 3][m1] = pa[1].w;
    dstB[kv * 4 + 0][m0] = pb[0].x; dstB[kv * 4 + 1][m0] = pb[0].y;
    dstB[kv * 4 + 2][m0] = pb[0].z; dstB[kv * 4 + 3][m0] = pb[0].w;
    dstB[kv * 4 + 0][m1] = pb[1].x; dstB[kv * 4 + 1][m1] = pb[1].y;
    dstB[kv * 4 + 2][m1] = pb[1].z; dstB[kv * 4 + 3][m1] = pb[1].w;
}

// 8x8 microtile FFMA2 step: a-frags broadcast-packed, b-frags pair-packed.
#define MICRO_FMA(a0, a1, b0, b1)                                              \
    do {                                                                       \
        unsigned long long ap[2][4] = {                                        \
            {pack2(a0.x, a0.x), pack2(a0.y, a0.y), pack2(a0.z, a0.z),          \
             pack2(a0.w, a0.w)},                                               \
            {pack2(a1.x, a1.x), pack2(a1.y, a1.y), pack2(a1.z, a1.z),          \
             pack2(a1.w, a1.w)}};                                              \
        unsigned long long bp[2][2] = {{pack2(b0.x, b0.y), pack2(b0.z, b0.w)}, \
                                       {pack2(b1.x, b1.y), pack2(b1.z, b1.w)}};\
        _Pragma("unroll") for (int mg = 0; mg < 2; mg++)                       \
            _Pragma("unroll") for (int mi = 0; mi < 4; mi++) {                 \
                ffma2(acc[mg][mi][0][0], ap[mg][mi], bp[0][0]);                \
                ffma2(acc[mg][mi][0][1], ap[mg][mi], bp[0][1]);                \
                ffma2(acc[mg][mi][1][0], ap[mg][mi], bp[1][0]);                \
                ffma2(acc[mg][mi][1][1], ap[mg][mi], bp[1][1]);                \
            }                                                                  \
    } while (0)

// ---------------------------------------------------------------------------
// GEMM1: E[b] = X[b] * X[b]^T   (128x128 tile, K = 4096, BK = 16)
// grid (2, 2, 32), 256 threads
// ---------------------------------------------------------------------------
__global__ __launch_bounds__(256) void gemm1_kernel(const float* __restrict__ x) {
    const int bz = blockIdx.z, by = blockIdx.y, bx = blockIdx.x;
    const float* Xb = x + (size_t)bz * Cn * Tn;
    const float* Arow = Xb + (size_t)by * 128 * Tn;
    const float* Brow = Xb + (size_t)bx * 128 * Tn;

    __shared__ __align__(16) float As[2][16][132];
    __shared__ __align__(16) float Bs[2][16][132];

    const int tid = threadIdx.x;
    const int tx = tid & 15, ty = tid >> 4;
    const int kv = tid & 3;
    const int m0 = tid >> 2, m1 = 64 + (tid >> 2);

    unsigned long long acc[2][4][2][2];
#pragma unroll
    for (int a = 0; a < 2; a++)
#pragma unroll
        for (int b = 0; b < 4; b++)
#pragma unroll
            for (int c = 0; c < 2; c++)
#pragma unroll
                for (int d = 0; d < 2; d++) acc[a][b][c][d] = 0ull;

    float4 pa[2], pb[2];
    pa[0] = *(const float4*)(Arow + (size_t)m0 * Tn + kv * 4);
    pa[1] = *(const float4*)(Arow + (size_t)m1 * Tn + kv * 4);
    pb[0] = *(const float4*)(Brow + (size_t)m0 * Tn + kv * 4);
    pb[1] = *(const float4*)(Brow + (size_t)m1 * Tn + kv * 4);
    store_tr(As[0], Bs[0], pa, pb, kv, m0, m1);
    __syncthreads();

    const int NC = Tn / 16;
#pragma unroll 1
    for (int c = 0; c < NC; ++c) {
        const int buf = c & 1;
        if (c + 1 < NC) {  // register prefetch of next chunk (hides DRAM/L2 lat)
            const int t0 = (c + 1) * 16;
            pa[0] = *(const float4*)(Arow + (size_t)m0 * Tn + t0 + kv * 4);
            pa[1] = *(const float4*)(Arow + (size_t)m1 * Tn + t0 + kv * 4);
            pb[0] = *(const float4*)(Brow + (size_t)m0 * Tn + t0 + kv * 4);
            pb[1] = *(const float4*)(Brow + (size_t)m1 * Tn + t0 + kv * 4);
        }
#pragma unroll
        for (int k = 0; k < 16; k++) {
            float4 a0 = *(const float4*)&As[buf][k][ty * 4];
            float4 a1 = *(const float4*)&As[buf][k][64 + ty * 4];
            float4 b0 = *(const float4*)&Bs[buf][k][tx * 4];
            float4 b1 = *(const float4*)&Bs[buf][k][64 + tx * 4];
            MICRO_FMA(a0, a1, b0, b1);
        }
        if (c + 1 < NC) {
            store_tr(As[buf ^ 1], Bs[buf ^ 1], pa, pb, kv, m0, m1);
            __syncthreads();
        }
    }

    float* E = (float*)g_attn4 + (size_t)bz * Cn * Cn;
#pragma unroll
    for (int mg = 0; mg < 2; mg++)
#pragma unroll
        for (int mi = 0; mi < 4; mi++) {
            int row = by * 128 + mg * 64 + ty * 4 + mi;
#pragma unroll
            for (int ng = 0; ng < 2; ng++) {
                int col = bx * 128 + ng * 64 + tx * 4;
                float4 v;
                unpack2(acc[mg][mi][ng][0], v.x, v.y);
                unpack2(acc[mg][mi][ng][1], v.z, v.w);
                *(float4*)(E + (size_t)row * Cn + col) = v;
            }
        }
}

// ---------------------------------------------------------------------------
// Softmax: attention = softmax(rowmax - E) = softmax(-E) = exp(min_e - e)/sum
// One block (256 threads) per row; 8192 blocks.
// ---------------------------------------------------------------------------
__global__ __launch_bounds__(256) void softmax_kernel() {
    const int row = blockIdx.x;
    float* E = (float*)g_attn4 + (size_t)row * Cn;
    const int tid = threadIdx.x;

    float e = E[tid];
    float v = e;
#pragma unroll
    for (int o = 16; o; o >>= 1) v = fminf(v, __shfl_xor_sync(0xffffffffu, v, o));

    __shared__ float red[8];
    __shared__ float bc[2];
    if ((tid & 31) == 0) red[tid >> 5] = v;
    __syncthreads();
    if (tid == 0) {
        float m = red[0];
#pragma unroll
        for (int i = 1; i < 8; i++) m = fminf(m, red[i]);
        bc[0] = m;
    }
    __syncthreads();

    float p = expf(bc[0] - e);
    v = p;
#pragma unroll
    for (int o = 16; o; o >>= 1) v += __shfl_xor_sync(0xffffffffu, v, o);
    if ((tid & 31) == 0) red[tid >> 5] = v;
    __syncthreads();
    if (tid == 0) {
        float s = 0.f;
#pragma unroll
        for (int i = 0; i < 8; i++) s += red[i];
        bc[1] = 1.0f / s;
    }
    __syncthreads();
    E[tid] = p * bc[1];
}

// ---------------------------------------------------------------------------
// GEMM2: out[b] = gamma * (A[b] * X[b]) + X[b]   (128x128 tile, K = 256)
// grid (32, 2, 32), 256 threads
// ---------------------------------------------------------------------------
__global__ __launch_bounds__(256) void gemm2_kernel(const float* __restrict__ x,
                                                    const float* __restrict__ gamma,
                                                    float* __restrict__ out) {
    const int bz = blockIdx.z, by = blockIdx.y, bxt = blockIdx.x;
    const float* Aatt = (const float*)g_attn4 + (size_t)bz * Cn * Cn + (size_t)by * 128 * Cn;
    const float* Xb = x + (size_t)bz * Cn * Tn;
    const int t0base = bxt * 128;

    __shared__ __align__(16) float As[2][16][132];
    __shared__ __align__(16) float Bs[2][16][132];

    const int tid = threadIdx.x;
    const int tx = tid & 15, ty = tid >> 4;
    const int kv = tid & 3;
    const int m0 = tid >> 2, m1 = 64 + (tid >> 2);
    const int jb = tid >> 5;   // B-tile: row within 8-row half
    const int nv = tid & 31;   // B-tile: float4 column

    unsigned long long acc[2][4][2][2];
#pragma unroll
    for (int a = 0; a < 2; a++)
#pragma unroll
        for (int b = 0; b < 4; b++)
#pragma unroll
            for (int c = 0; c < 2; c++)
#pragma unroll
                for (int d = 0; d < 2; d++) acc[a][b][c][d] = 0ull;

    float4 pa[2], pb[2];
    pa[0] = *(const float4*)(Aatt + (size_t)m0 * Cn + kv * 4);
    pa[1] = *(const float4*)(Aatt + (size_t)m1 * Cn + kv * 4);
    pb[0] = *(const float4*)(Xb + (size_t)jb * Tn + t0base + nv * 4);
    pb[1] = *(const float4*)(Xb + (size_t)(8 + jb) * Tn + t0base + nv * 4);
    {   // A transposed, B direct (t-contiguous rows)
        store_tr(As[0], As[0], pa, pa, kv, m0, m1);  // A only (dstB aliased, same data twice is harmless but wasteful)
        *(float4*)&Bs[0][jb][nv * 4] = pb[0];
        *(float4*)&Bs[0][8 + jb][nv * 4] = pb[1];
    }
    __syncthreads();

    const int NC = Cn / 16;
#pragma unroll 1
    for (int c = 0; c < NC; ++c) {
        const int buf = c & 1;
        if (c + 1 < NC) {
            const int j0 = (c + 1) * 16;
            pa[0] = *(const float4*)(Aatt + (size_t)m0 * Cn + j0 + kv * 4);
            pa[1] = *(const float4*)(Aatt + (size_t)m1 * Cn + j0 + kv * 4);
            pb[0] = *(const float4*)(Xb + (size_t)(j0 + jb) * Tn + t0base + nv * 4);
            pb[1] = *(const float4*)(Xb + (size_t)(j0 + 8 + jb) * Tn + t0base + nv * 4);
        }
#pragma unroll
        for (int k = 0; k < 16; k++) {
            float4 a0 = *(const float4*)&As[buf][k][ty * 4];
            float4 a1 = *(const float4*)&As[buf][k][64 + ty * 4];
            float4 b0 = *(const float4*)&Bs[buf][k][tx * 4];
            float4 b1 = *(const float4*)&Bs[buf][k][64 + tx * 4];
            MICRO_FMA(a0, a1, b0, b1);
        }
        if (c + 1 < NC) {
            const int nbuf = buf ^ 1;
            As[nbuf][kv * 4 + 0][m0] = pa[0].x; As[nbuf][kv * 4 + 1][m0] = pa[0].y;
            As[nbuf][kv * 4 + 2][m0] = pa[0].z; As[nbuf][kv * 4 + 3][m0] = pa[0].w;
            As[nbuf][kv * 4 + 0][m1] = pa[1].x; As[nbuf][kv * 4 + 1][m1] = pa[1].y;
            As[nbuf][kv * 4 + 2][m1] = pa[1].z; As[nbuf][kv * 4 + 3][m1] = pa[1].w;
            *(float4*)&Bs[nbuf][jb][nv * 4] = pb[0];
            *(float4*)&Bs[nbuf][8 + jb][nv * 4] = pb[1];
            __syncthreads();
        }
    }

    const float gm = __ldg(gamma);
    float* Ob = out + (size_t)bz * Cn * Tn;
#pragma unroll
    for (int mg = 0; mg < 2; mg++)
#pragma unroll
        for (int mi = 0; mi < 4; mi++) {
            int row = by * 128 + mg * 64 + ty * 4 + mi;
#pragma unroll
            for (int ng = 0; ng < 2; ng++) {
                int col = t0base + ng * 64 + tx * 4;
                float4 xv = *(const float4*)(Xb + (size_t)row * Tn + col);
                float4 v;
                unpack2(acc[mg][mi][ng][0], v.x, v.y);
                unpack2(acc[mg][mi][ng][1], v.z, v.w);
                v.x = gm * v.x + xv.x;
                v.y = gm * v.y + xv.y;
                v.z = gm * v.z + xv.z;
                v.w = gm * v.w + xv.w;
                *(float4*)(Ob + (size_t)row * Tn + col) = v;
            }
        }
}

// ---------------------------------------------------------------------------
extern "C" void kernel_launch(void* const* d_in, const int* in_sizes, int n_in,
                              void* d_out, int out_size) {
    (void)in_sizes; (void)n_in; (void)out_size;
    const float* x = (const float*)d_in[0];
    const float* gamma = (const float*)d_in[1];
    float* out = (float*)d_out;

    dim3 g1(Cn / 128, Cn / 128, Bn);   // (2, 2, 32)
    gemm1_kernel<<<g1, 256>>>(x);

    softmax_kernel<<<Bn * Cn, 256>>>();

    dim3 g2(Tn / 128, Cn / 128, Bn);   // (32, 2, 32)
    gemm2_kernel<<<g2, 256>>>(x, gamma, out);
}

// round 7
// speedup vs baseline: 1.1060x; 1.1060x over previous
#include <cuda_runtime.h>
#include <cstdint>

#define Bn 32
#define Cn 256
#define Tn 4096
#define BK 32
#define STRD 36                    // smem row stride in 32-bit words
#define TILEW (128 * STRD)         // words per 128x32 tile (padded)
#define SMEM_WORDS (8 * TILEW)     // 2 stages x 4 tiles (AH, AL, BH, BL)
#define SMEM_BYTES (SMEM_WORDS * 4)  // 147456

// 8 MB scratch for per-batch energy/attention matrices.
__device__ float4 g_attn4[(size_t)Bn * Cn * Cn / 4];

// ---------------------------------------------------------------------------
// TF32 split helpers (cuBLAS-style 3xTF32: x = hi + lo, both rounded to tf32)
// ---------------------------------------------------------------------------
__device__ __forceinline__ uint32_t f2tf32(float x) {
    uint32_t u;
    asm("cvt.rna.tf32.f32 %0, %1;" : "=r"(u) : "f"(x));
    return u;
}
__device__ __forceinline__ void split_tf32(float x, uint32_t& h, uint32_t& l) {
    h = f2tf32(x);
    l = f2tf32(x - __uint_as_float(h));
}

// Warp-level tensor-core MMA (baseline sm_80+ feature — works on sm_103 target).
__device__ __forceinline__ void mma_m16n8k8(float* d, const uint32_t* a,
                                            const uint32_t* b) {
    asm volatile(
        "mma.sync.aligned.m16n8k8.row.col.f32.tf32.tf32.f32 "
        "{%0,%1,%2,%3}, {%4,%5,%6,%7}, {%8,%9}, {%0,%1,%2,%3};"
        : "+f"(d[0]), "+f"(d[1]), "+f"(d[2]), "+f"(d[3])
        : "r"(a[0]), "r"(a[1]), "r"(a[2]), "r"(a[3]), "r"(b[0]), "r"(b[1]));
}

// ---------------------------------------------------------------------------
// Row-major 128xBK loader: fetch to regs (coalesced float4), stage = split+STS.
// Thread map: idx = i*256+tid -> row = idx>>3 (0..127), q = idx&7 (float4 col).
// STS.128 at word off row*36 + 4q: conflict-free per 8-lane phase.
// ---------------------------------------------------------------------------
__device__ __forceinline__ void fetch_rm(const float* __restrict__ G, int ld,
                                         int k0, float4* v, int tid) {
#pragma unroll
    for (int i = 0; i < 4; i++) {
        int idx = i * 256 + tid;
        int row = idx >> 3, q = idx & 7;
        v[i] = *(const float4*)(G + (size_t)row * ld + k0 + q * 4);
    }
}
__device__ __forceinline__ void stage_rm(uint32_t* __restrict__ H,
                                         uint32_t* __restrict__ L,
                                         const float4* v, int tid) {
#pragma unroll
    for (int i = 0; i < 4; i++) {
        int idx = i * 256 + tid;
        int row = idx >> 3, q = idx & 7;
        uint32_t h0, h1, h2, h3, l0, l1, l2, l3;
        split_tf32(v[i].x, h0, l0);
        split_tf32(v[i].y, h1, l1);
        split_tf32(v[i].z, h2, l2);
        split_tf32(v[i].w, h3, l3);
        uint32_t off = (uint32_t)(row * STRD + q * 4);
        *(uint4*)(H + off) = make_uint4(h0, h1, h2, h3);
        *(uint4*)(L + off) = make_uint4(l0, l1, l2, l3);
    }
}

// ---------------------------------------------------------------------------
// Compute one BK=32 chunk: 4 k8-steps x 3 split-products x 16 atoms per warp.
// Fragment LDS word = (base row)*36 + col: lane part = gid*4 + tig -> all 32
// banks distinct -> conflict-free.
// ---------------------------------------------------------------------------
__device__ __forceinline__ void compute_chunk(const uint32_t* __restrict__ st,
                                              float acc[4][4][4], int warpM,
                                              int warpN, int lane) {
    const int gid = lane >> 2, tig = lane & 3;
    const uint32_t* AH = st;
    const uint32_t* AL = st + TILEW;
    const uint32_t* BH = st + 2 * TILEW;
    const uint32_t* BL = st + 3 * TILEW;
#pragma unroll
    for (int ks = 0; ks < 4; ks++) {
        const int kc = ks * 8 + tig;
        uint32_t ah[4][4], bh[4][2];
#pragma unroll
        for (int ma = 0; ma < 4; ma++) {
            int r = (warpM + ma * 16 + gid) * STRD + kc;
            ah[ma][0] = AH[r];
            ah[ma][1] = AH[r + 8 * STRD];
            ah[ma][2] = AH[r + 4];
            ah[ma][3] = AH[r + 8 * STRD + 4];
        }
#pragma unroll
        for (int na = 0; na < 4; na++) {
            int r = (warpN + na * 8 + gid) * STRD + kc;
            bh[na][0] = BH[r];
            bh[na][1] = BH[r + 4];
        }
#pragma unroll
        for (int ma = 0; ma < 4; ma++)
#pragma unroll
            for (int na = 0; na < 4; na++) mma_m16n8k8(acc[ma][na], ah[ma], bh[na]);
        {   // hi * lo
            uint32_t bl[4][2];
#pragma unroll
            for (int na = 0; na < 4; na++) {
                int r = (warpN + na * 8 + gid) * STRD + kc;
                bl[na][0] = BL[r];
                bl[na][1] = BL[r + 4];
            }
#pragma unroll
            for (int ma = 0; ma < 4; ma++)
#pragma unroll
                for (int na = 0; na < 4; na++) mma_m16n8k8(acc[ma][na], ah[ma], bl[na]);
        }
        {   // lo * hi
            uint32_t al[4][4];
#pragma unroll
            for (int ma = 0; ma < 4; ma++) {
                int r = (warpM + ma * 16 + gid) * STRD + kc;
                al[ma][0] = AL[r];
                al[ma][1] = AL[r + 8 * STRD];
                al[ma][2] = AL[r + 4];
                al[ma][3] = AL[r + 8 * STRD + 4];
            }
#pragma unroll
            for (int ma = 0; ma < 4; ma++)
#pragma unroll
                for (int na = 0; na < 4; na++) mma_m16n8k8(acc[ma][na], al[ma], bh[na]);
        }
    }
}

// ---------------------------------------------------------------------------
// GEMM1: E[b] = X[b] * X[b]^T.  grid (2,2,32), 256 threads.
// Both operands are X rows ([row][k], k contiguous) -> direct row-major stage.
// ---------------------------------------------------------------------------
__global__ __launch_bounds__(256, 1) void gemm1_mma(const float* __restrict__ x) {
    extern __shared__ uint32_t smw[];
    const int tid = threadIdx.x, lane = tid & 31, wid = tid >> 5;
    const int warpM = (wid >> 2) * 64, warpN = (wid & 3) * 32;
    const float* Xb = x + (size_t)blockIdx.z * Cn * Tn;
    const float* Ag = Xb + (size_t)blockIdx.y * 128 * Tn;
    const float* Bg = Xb + (size_t)blockIdx.x * 128 * Tn;

    float acc[4][4][4];
#pragma unroll
    for (int a = 0; a < 4; a++)
#pragma unroll
        for (int b = 0; b < 4; b++)
#pragma unroll
            for (int c = 0; c < 4; c++) acc[a][b][c] = 0.f;

    float4 va[4], vb[4];
    fetch_rm(Ag, Tn, 0, va, tid);
    fetch_rm(Bg, Tn, 0, vb, tid);
    stage_rm(smw, smw + TILEW, va, tid);
    stage_rm(smw + 2 * TILEW, smw + 3 * TILEW, vb, tid);
    __syncthreads();

    const int NC = Tn / BK;
#pragma unroll 1
    for (int c = 0; c < NC; c++) {
        const int s = c & 1;
        if (c + 1 < NC) {
            fetch_rm(Ag, Tn, (c + 1) * BK, va, tid);
            fetch_rm(Bg, Tn, (c + 1) * BK, vb, tid);
        }
        compute_chunk(smw + s * 4 * TILEW, acc, warpM, warpN, lane);
        if (c + 1 < NC) {
            uint32_t* nb = smw + (s ^ 1) * 4 * TILEW;
            stage_rm(nb, nb + TILEW, va, tid);
            stage_rm(nb + 2 * TILEW, nb + 3 * TILEW, vb, tid);
            __syncthreads();
        }
    }

    float* E = (float*)g_attn4 + (size_t)blockIdx.z * Cn * Cn;
    const int gid = lane >> 2, tig = lane & 3;
#pragma unroll
    for (int ma = 0; ma < 4; ma++)
#pragma unroll
        for (int na = 0; na < 4; na++) {
            int r0 = blockIdx.y * 128 + warpM + ma * 16 + gid;
            int cc = blockIdx.x * 128 + warpN + na * 8 + 2 * tig;
            *(float2*)(E + (size_t)r0 * Cn + cc) =
                make_float2(acc[ma][na][0], acc[ma][na][1]);
            *(float2*)(E + (size_t)(r0 + 8) * Cn + cc) =
                make_float2(acc[ma][na][2], acc[ma][na][3]);
        }
}

// ---------------------------------------------------------------------------
// Softmax: attention = softmax(rowmax - E) = exp(min_e - e)/sum. 1 block/row.
// ---------------------------------------------------------------------------
__global__ __launch_bounds__(256) void softmax_kernel() {
    const int row = blockIdx.x;
    float* E = (float*)g_attn4 + (size_t)row * Cn;
    const int tid = threadIdx.x;

    float e = E[tid];
    float v = e;
#pragma unroll
    for (int o = 16; o; o >>= 1) v = fminf(v, __shfl_xor_sync(0xffffffffu, v, o));
    __shared__ float red[8];
    __shared__ float bc[2];
    if ((tid & 31) == 0) red[tid >> 5] = v;
    __syncthreads();
    if (tid == 0) {
        float m = red[0];
#pragma unroll
        for (int i = 1; i < 8; i++) m = fminf(m, red[i]);
        bc[0] = m;
    }
    __syncthreads();
    float p = expf(bc[0] - e);
    v = p;
#pragma unroll
    for (int o = 16; o; o >>= 1) v += __shfl_xor_sync(0xffffffffu, v, o);
    if ((tid & 31) == 0) red[tid >> 5] = v;
    __syncthreads();
    if (tid == 0) {
        float s = 0.f;
#pragma unroll
        for (int i = 0; i < 8; i++) s += red[i];
        bc[1] = 1.0f / s;
    }
    __syncthreads();
    E[tid] = p * bc[1];
}

// ---------------------------------------------------------------------------
// GEMM2: out[b] = gamma * (Attn[b] * X[b]) + X[b].  grid (32,2,32), 256 thr.
// A = Attn rows (k contiguous -> row-major stage). B needs col-major [k=j][n=t]
// = smem [t][j]: load X[j][t] coalesced along t, transpose during STS
// (4-way STS conflicts at stride 36; stores are issue-only, acceptable).
// ---------------------------------------------------------------------------
__global__ __launch_bounds__(256, 1) void gemm2_mma(const float* __restrict__ x,
                                                    const float* __restrict__ gamma,
                                                    float* __restrict__ out) {
    extern __shared__ uint32_t smw[];
    const int tid = threadIdx.x, lane = tid & 31, wid = tid >> 5;
    const int warpM = (wid >> 2) * 64, warpN = (wid & 3) * 32;
    const int bz = blockIdx.z, by = blockIdx.y, t0 = blockIdx.x * 128;
    const float* Aatt =
        (const float*)g_attn4 + (size_t)bz * Cn * Cn + (size_t)by * 128 * Cn;
    const float* Xb = x + (size_t)bz * Cn * Tn;

    const int bj = wid * 4 + (lane >> 3);   // B fetch: source row j (0..31)
    const int bt = lane & 7;                // B fetch: t4 low bits

    float acc[4][4][4];
#pragma unroll
    for (int a = 0; a < 4; a++)
#pragma unroll
        for (int b = 0; b < 4; b++)
#pragma unroll
            for (int c = 0; c < 4; c++) acc[a][b][c] = 0.f;

    float4 va[4], vb[4];
    auto fetchB = [&](int j0) {
#pragma unroll
        for (int tb = 0; tb < 4; tb++) {
            int t4 = tb * 8 + bt;
            vb[tb] = *(const float4*)(Xb + (size_t)(j0 + bj) * Tn + t0 + t4 * 4);
        }
    };
    auto stageB = [&](uint32_t* BH, uint32_t* BL) {
#pragma unroll
        for (int tb = 0; tb < 4; tb++) {
            int t4 = tb * 8 + bt;
            const float* pv = (const float*)&vb[tb];
#pragma unroll
            for (int r = 0; r < 4; r++) {
                uint32_t h, l;
                split_tf32(pv[r], h, l);
                uint32_t off = (uint32_t)((t4 * 4 + r) * STRD + bj);
                BH[off] = h;
                BL[off] = l;
            }
        }
    };

    fetch_rm(Aatt, Cn, 0, va, tid);
    fetchB(0);
    stage_rm(smw, smw + TILEW, va, tid);
    stageB(smw + 2 * TILEW, smw + 3 * TILEW);
    __syncthreads();

    const int NC = Cn / BK;   // 8
#pragma unroll 1
    for (int c = 0; c < NC; c++) {
        const int s = c & 1;
        if (c + 1 < NC) {
            fetch_rm(Aatt, Cn, (c + 1) * BK, va, tid);
            fetchB((c + 1) * BK);
        }
        compute_chunk(smw + s * 4 * TILEW, acc, warpM, warpN, lane);
        if (c + 1 < NC) {
            uint32_t* nb = smw + (s ^ 1) * 4 * TILEW;
            stage_rm(nb, nb + TILEW, va, tid);
            stageB(nb + 2 * TILEW, nb + 3 * TILEW);
            __syncthreads();
        }
    }

    const float gm = __ldg(gamma);
    float* Ob = out + (size_t)bz * Cn * Tn;
    const int gid = lane >> 2, tig = lane & 3;
#pragma unroll
    for (int ma = 0; ma < 4; ma++)
#pragma unroll
        for (int na = 0; na < 4; na++) {
            int r0 = by * 128 + warpM + ma * 16 + gid;
            int cc = t0 + warpN + na * 8 + 2 * tig;
            size_t o0 = (size_t)r0 * Tn + cc;
            size_t o1 = (size_t)(r0 + 8) * Tn + cc;
            float2 x0 = *(const float2*)(Xb + o0);
            float2 x1 = *(const float2*)(Xb + o1);
            *(float2*)(Ob + o0) = make_float2(gm * acc[ma][na][0] + x0.x,
                                              gm * acc[ma][na][1] + x0.y);
            *(float2*)(Ob + o1) = make_float2(gm * acc[ma][na][2] + x1.x,
                                              gm * acc[ma][na][3] + x1.y);
        }
}

// ---------------------------------------------------------------------------
extern "C" void kernel_launch(void* const* d_in, const int* in_sizes, int n_in,
                              void* d_out, int out_size) {
    (void)in_sizes; (void)n_in; (void)out_size;
    const float* x = (const float*)d_in[0];
    const float* gamma = (const float*)d_in[1];
    float* out = (float*)d_out;

    cudaFuncSetAttribute(gemm1_mma, cudaFuncAttributeMaxDynamicSharedMemorySize,
                         SMEM_BYTES);
    cudaFuncSetAttribute(gemm2_mma, cudaFuncAttributeMaxDynamicSharedMemorySize,
                         SMEM_BYTES);

    gemm1_mma<<<dim3(Cn / 128, Cn / 128, Bn), 256, SMEM_BYTES>>>(x);
    softmax_kernel<<<Bn * Cn, 256>>>();
    gemm2_mma<<<dim3(Tn / 128, Cn / 128, Bn), 256, SMEM_BYTES>>>(x, gamma, out);
}

// round 8
// speedup vs baseline: 1.3954x; 1.2617x over previous
#include <cuda_runtime.h>
#include <cuda_fp16.h>
#include <cstdint>

#define Bn 32
#define Cn 256
#define Tn 4096
#define TILE_W 2048   // 32-bit words per 128x32-f16 tile (128 rows x 16 words)

// Static device scratch (allocation-guard legal).
__device__ float4   g_e4[(size_t)Bn * Cn * Cn / 4];      //  8 MB energy (fp32)
__device__ uint32_t g_ah32[(size_t)Bn * Cn * Cn / 2];    //  4 MB attn hi (f16)
__device__ uint32_t g_al32[(size_t)Bn * Cn * Cn / 2];    //  4 MB attn lo (f16)
__device__ uint32_t g_xth32[(size_t)Bn * Tn * Cn / 2];   // 67 MB X^T hi (f16)

// ---------------------------------------------------------------------------
// Helpers
// ---------------------------------------------------------------------------
__device__ __forceinline__ uint32_t packh2(__half a, __half b) {
    return (uint32_t)__half_as_ushort(a) | ((uint32_t)__half_as_ushort(b) << 16);
}

// Smem tile layout: 128 rows x 16 words; word = f16 k-pair. Logical pair p
// (p = k>>1, 0..15) lives in quad Q = (p>>3)*4 + (p&3), slot (p>>2)&1; the
// quad is XOR-swizzled by row&3 so fragment LDS.64 hits the 2-phase floor.
__device__ __forceinline__ int swz(int row, int p) {
    return row * 16 + (((p >> 3) << 2) + ((p & 3) ^ (row & 3))) * 2 + ((p >> 2) & 1);
}
// Fragment quad load: returns (pair k=16ks+2tig, pair k=16ks+2tig+8).
__device__ __forceinline__ uint2 ldq(const uint32_t* t, int r, int ks, int tig) {
    return *(const uint2*)(t + r * 16 + (ks * 4 + (tig ^ (r & 3))) * 2);
}

__device__ __forceinline__ void mma_f16(float* d, const uint32_t* a, const uint32_t* b) {
    asm volatile(
        "mma.sync.aligned.m16n8k16.row.col.f32.f16.f16.f32 "
        "{%0,%1,%2,%3}, {%4,%5,%6,%7}, {%8,%9}, {%0,%1,%2,%3};"
        : "+f"(d[0]), "+f"(d[1]), "+f"(d[2]), "+f"(d[3])
        : "r"(a[0]), "r"(a[1]), "r"(a[2]), "r"(a[3]), "r"(b[0]), "r"(b[1]));
}

// ---------------------------------------------------------------------------
// Fetch/stage (512 threads). fp32 source: split into f16 hi+lo tiles.
// ---------------------------------------------------------------------------
__device__ __forceinline__ void fetch_f32(const float* __restrict__ G, int ld,
                                          int k0, float4* v, int tid) {
#pragma unroll
    for (int it = 0; it < 2; it++) {
        int idx = it * 512 + tid, row = idx >> 3, q = idx & 7;
        v[it] = *(const float4*)(G + (size_t)row * ld + k0 + q * 4);
    }
}
__device__ __forceinline__ void stage_f32(uint32_t* __restrict__ H,
                                          uint32_t* __restrict__ L,
                                          const float4* v, int tid) {
#pragma unroll
    for (int it = 0; it < 2; it++) {
        int idx = it * 512 + tid, row = idx >> 3, q = idx & 7;
        float4 w = v[it];
        __half h0 = __float2half_rn(w.x), h1 = __float2half_rn(w.y);
        __half h2 = __float2half_rn(w.z), h3 = __float2half_rn(w.w);
        H[swz(row, 2 * q)]     = packh2(h0, h1);
        H[swz(row, 2 * q + 1)] = packh2(h2, h3);
        L[swz(row, 2 * q)]     = packh2(__float2half_rn(w.x - __half2float(h0)),
                                        __float2half_rn(w.y - __half2float(h1)));
        L[swz(row, 2 * q + 1)] = packh2(__float2half_rn(w.z - __half2float(h2)),
                                        __float2half_rn(w.w - __half2float(h3)));
    }
}
// Pre-split u32 (f16-pair) source.
__device__ __forceinline__ void fetch_u32(const uint32_t* __restrict__ G,
                                          int k0w, uint2* v, int tid) {
#pragma unroll
    for (int it = 0; it < 2; it++) {
        int idx = it * 512 + tid, row = idx >> 3, q = idx & 7;
        v[it] = *(const uint2*)(G + (size_t)row * 128 + k0w + 2 * q);
    }
}
__device__ __forceinline__ void stage_u32(uint32_t* __restrict__ T,
                                          const uint2* v, int tid) {
#pragma unroll
    for (int it = 0; it < 2; it++) {
        int idx = it * 512 + tid, row = idx >> 3, q = idx & 7;
        T[swz(row, 2 * q)]     = v[it].x;
        T[swz(row, 2 * q + 1)] = v[it].y;
    }
}

// ---------------------------------------------------------------------------
// Per-chunk compute, 32x32 warp tile (2 m-atoms x 4 n-atoms), BK=32 (2 ksteps)
// ---------------------------------------------------------------------------
__device__ __forceinline__ void chunk3(const uint32_t* sb, float acc[8][4],
                                       int warpM, int warpN, int gid, int tig) {
    const uint32_t *AH = sb, *AL = sb + TILE_W, *BH = sb + 2 * TILE_W, *BL = sb + 3 * TILE_W;
#pragma unroll
    for (int ks = 0; ks < 2; ks++) {
        uint32_t ah[2][4], al[2][4], bh[4][2], bl[4][2];
#pragma unroll
        for (int ma = 0; ma < 2; ma++) {
            int r0 = warpM + ma * 16 + gid;
            uint2 u0 = ldq(AH, r0, ks, tig), u1 = ldq(AH, r0 + 8, ks, tig);
            ah[ma][0] = u0.x; ah[ma][1] = u1.x; ah[ma][2] = u0.y; ah[ma][3] = u1.y;
            uint2 v0 = ldq(AL, r0, ks, tig), v1 = ldq(AL, r0 + 8, ks, tig);
            al[ma][0] = v0.x; al[ma][1] = v1.x; al[ma][2] = v0.y; al[ma][3] = v1.y;
        }
#pragma unroll
        for (int na = 0; na < 4; na++) {
            int r = warpN + na * 8 + gid;
            uint2 u = ldq(BH, r, ks, tig); bh[na][0] = u.x; bh[na][1] = u.y;
            uint2 v = ldq(BL, r, ks, tig); bl[na][0] = v.x; bl[na][1] = v.y;
        }
#pragma unroll
        for (int ma = 0; ma < 2; ma++)
#pragma unroll
            for (int na = 0; na < 4; na++) {
                float* d = acc[ma * 4 + na];
                mma_f16(d, ah[ma], bh[na]);
                mma_f16(d, al[ma], bh[na]);
                mma_f16(d, ah[ma], bl[na]);
            }
    }
}
__device__ __forceinline__ void chunk2(const uint32_t* sb, float acc[8][4],
                                       int warpM, int warpN, int gid, int tig) {
    const uint32_t *AH = sb, *AL = sb + TILE_W, *BH = sb + 2 * TILE_W;
#pragma unroll
    for (int ks = 0; ks < 2; ks++) {
        uint32_t ah[2][4], al[2][4], bh[4][2];
#pragma unroll
        for (int ma = 0; ma < 2; ma++) {
            int r0 = warpM + ma * 16 + gid;
            uint2 u0 = ldq(AH, r0, ks, tig), u1 = ldq(AH, r0 + 8, ks, tig);
            ah[ma][0] = u0.x; ah[ma][1] = u1.x; ah[ma][2] = u0.y; ah[ma][3] = u1.y;
            uint2 v0 = ldq(AL, r0, ks, tig), v1 = ldq(AL, r0 + 8, ks, tig);
            al[ma][0] = v0.x; al[ma][1] = v1.x; al[ma][2] = v0.y; al[ma][3] = v1.y;
        }
#pragma unroll
        for (int na = 0; na < 4; na++) {
            int r = warpN + na * 8 + gid;
            uint2 u = ldq(BH, r, ks, tig); bh[na][0] = u.x; bh[na][1] = u.y;
        }
#pragma unroll
        for (int ma = 0; ma < 2; ma++)
#pragma unroll
            for (int na = 0; na < 4; na++) {
                float* d = acc[ma * 4 + na];
                mma_f16(d, ah[ma], bh[na]);
                mma_f16(d, al[ma], bh[na]);
            }
    }
}

// ---------------------------------------------------------------------------
// Transpose + f16-round: xt_h[b][t][c] = f16(x[b][c][t])
// ---------------------------------------------------------------------------
__global__ __launch_bounds__(256) void transpose_h(const float* __restrict__ x) {
    __shared__ float tile[32][33];
    const int b = blockIdx.z, c0 = blockIdx.y * 32, t0 = blockIdx.x * 32;
    const int tx = threadIdx.x, ty = threadIdx.y;
    const float* Xb = x + ((size_t)b * Cn + c0) * Tn + t0;
    __half* Xt = (__half*)g_xth32 + ((size_t)b * Tn + t0) * Cn + c0;
#pragma unroll
    for (int r = 0; r < 32; r += 8) tile[ty + r][tx] = Xb[(size_t)(ty + r) * Tn + tx];
    __syncthreads();
#pragma unroll
    for (int r = 0; r < 32; r += 8)
        Xt[(size_t)(ty + r) * Cn + tx] = __float2half_rn(tile[tx][ty + r]);
}

// ---------------------------------------------------------------------------
// GEMM1: E[b] = X[b] * X[b]^T  (3xFP16 split).  grid (2,2,32), 512 threads.
// ---------------------------------------------------------------------------
__global__ __launch_bounds__(512, 1) void gemm1_h(const float* __restrict__ x) {
    extern __shared__ uint32_t sm[];
    const int tid = threadIdx.x, lane = tid & 31, wid = tid >> 5;
    const int gid = lane >> 2, tig = lane & 3;
    const int warpM = (wid >> 2) * 32, warpN = (wid & 3) * 32;
    const float* Xb = x + (size_t)blockIdx.z * Cn * Tn;
    const float* Ag = Xb + (size_t)blockIdx.y * 128 * Tn;
    const float* Bg = Xb + (size_t)blockIdx.x * 128 * Tn;

    float acc[8][4];
#pragma unroll
    for (int a = 0; a < 8; a++)
#pragma unroll
        for (int c = 0; c < 4; c++) acc[a][c] = 0.f;

    float4 va[2], vb[2];
    fetch_f32(Ag, Tn, 0, va, tid);
    fetch_f32(Bg, Tn, 0, vb, tid);
    stage_f32(sm, sm + TILE_W, va, tid);
    stage_f32(sm + 2 * TILE_W, sm + 3 * TILE_W, vb, tid);
    __syncthreads();

    const int NC = Tn / 32;
#pragma unroll 1
    for (int c = 0; c < NC; c++) {
        const int s = c & 1;
        if (c + 1 < NC) {
            fetch_f32(Ag, Tn, (c + 1) * 32, va, tid);
            fetch_f32(Bg, Tn, (c + 1) * 32, vb, tid);
        }
        chunk3(sm + s * 4 * TILE_W, acc, warpM, warpN, gid, tig);
        if (c + 1 < NC) {
            uint32_t* nb = sm + (s ^ 1) * 4 * TILE_W;
            stage_f32(nb, nb + TILE_W, va, tid);
            stage_f32(nb + 2 * TILE_W, nb + 3 * TILE_W, vb, tid);
            __syncthreads();
        }
    }

    float* E = (float*)g_e4 + (size_t)blockIdx.z * Cn * Cn;
#pragma unroll
    for (int ma = 0; ma < 2; ma++)
#pragma unroll
        for (int na = 0; na < 4; na++) {
            const float* d = acc[ma * 4 + na];
            int r0 = blockIdx.y * 128 + warpM + ma * 16 + gid;
            int cc = blockIdx.x * 128 + warpN + na * 8 + 2 * tig;
            *(float2*)(E + (size_t)r0 * Cn + cc) = make_float2(d[0], d[1]);
            *(float2*)(E + (size_t)(r0 + 8) * Cn + cc) = make_float2(d[2], d[3]);
        }
}

// ---------------------------------------------------------------------------
// Softmax: w = exp(min_e - e)/sum (== softmax(rowmax - e)); writes f16 h+l.
// ---------------------------------------------------------------------------
__global__ __launch_bounds__(256) void softmax_kernel() {
    const int row = blockIdx.x;
    const float* E = (float*)g_e4 + (size_t)row * Cn;
    const int tid = threadIdx.x;

    float e = E[tid];
    float v = e;
#pragma unroll
    for (int o = 16; o; o >>= 1) v = fminf(v, __shfl_xor_sync(0xffffffffu, v, o));
    __shared__ float red[8];
    __shared__ float bc[2];
    if ((tid & 31) == 0) red[tid >> 5] = v;
    __syncthreads();
    if (tid == 0) {
        float m = red[0];
#pragma unroll
        for (int i = 1; i < 8; i++) m = fminf(m, red[i]);
        bc[0] = m;
    }
    __syncthreads();
    float p = expf(bc[0] - e);
    v = p;
#pragma unroll
    for (int o = 16; o; o >>= 1) v += __shfl_xor_sync(0xffffffffu, v, o);
    if ((tid & 31) == 0) red[tid >> 5] = v;
    __syncthreads();
    if (tid == 0) {
        float s = 0.f;
#pragma unroll
        for (int i = 0; i < 8; i++) s += red[i];
        bc[1] = 1.0f / s;
    }
    __syncthreads();
    float w = p * bc[1];
    __half h = __float2half_rn(w);
    ((__half*)g_ah32)[(size_t)row * Cn + tid] = h;
    ((__half*)g_al32)[(size_t)row * Cn + tid] =
        __float2half_rn(w - __half2float(h));
}

// ---------------------------------------------------------------------------
// GEMM2: out = gamma * (Attn * X) + X.  A = attn h+l, B = X^T hi (2 products).
// grid (32,2,32), 512 threads.
// ---------------------------------------------------------------------------
__global__ __launch_bounds__(512, 1) void gemm2_h(const float* __restrict__ x,
                                                  const float* __restrict__ gamma,
                                                  float* __restrict__ out) {
    extern __shared__ uint32_t sm[];
    const int tid = threadIdx.x, lane = tid & 31, wid = tid >> 5;
    const int gid = lane >> 2, tig = lane & 3;
    const int warpM = (wid >> 2) * 32, warpN = (wid & 3) * 32;
    const int bz = blockIdx.z, by = blockIdx.y, t0 = blockIdx.x * 128;

    const uint32_t* Ah = g_ah32 + ((size_t)bz * Cn + by * 128) * 128;
    const uint32_t* Al = g_al32 + ((size_t)bz * Cn + by * 128) * 128;
    const uint32_t* Bh = g_xth32 + ((size_t)bz * Tn + t0) * 128;

    float acc[8][4];
#pragma unroll
    for (int a = 0; a < 8; a++)
#pragma unroll
        for (int c = 0; c < 4; c++) acc[a][c] = 0.f;

    uint2 vah[2], val[2], vbh[2];
    fetch_u32(Ah, 0, vah, tid);
    fetch_u32(Al, 0, val, tid);
    fetch_u32(Bh, 0, vbh, tid);
    stage_u32(sm, vah, tid);
    stage_u32(sm + TILE_W, val, tid);
    stage_u32(sm + 2 * TILE_W, vbh, tid);
    __syncthreads();

    const int NC = Cn / 32;   // 8
#pragma unroll 1
    for (int c = 0; c < NC; c++) {
        const int s = c & 1;
        if (c + 1 < NC) {
            fetch_u32(Ah, (c + 1) * 16, vah, tid);
            fetch_u32(Al, (c + 1) * 16, val, tid);
            fetch_u32(Bh, (c + 1) * 16, vbh, tid);
        }
        chunk2(sm + s * 3 * TILE_W, acc, warpM, warpN, gid, tig);
        if (c + 1 < NC) {
            uint32_t* nb = sm + (s ^ 1) * 3 * TILE_W;
            stage_u32(nb, vah, tid);
            stage_u32(nb + TILE_W, val, tid);
            stage_u32(nb + 2 * TILE_W, vbh, tid);
            __syncthreads();
        }
    }

    const float gm = __ldg(gamma);
    const float* Xb = x + (size_t)bz * Cn * Tn;
    float* Ob = out + (size_t)bz * Cn * Tn;
#pragma unroll
    for (int ma = 0; ma < 2; ma++)
#pragma unroll
        for (int na = 0; na < 4; na++) {
            const float* d = acc[ma * 4 + na];
            int r0 = by * 128 + warpM + ma * 16 + gid;
            int cc = t0 + warpN + na * 8 + 2 * tig;
            size_t o0 = (size_t)r0 * Tn + cc;
            size_t o1 = (size_t)(r0 + 8) * Tn + cc;
            float2 x0 = *(const float2*)(Xb + o0);
            float2 x1 = *(const float2*)(Xb + o1);
            *(float2*)(Ob + o0) = make_float2(gm * d[0] + x0.x, gm * d[1] + x0.y);
            *(float2*)(Ob + o1) = make_float2(gm * d[2] + x1.x, gm * d[3] + x1.y);
        }
}

// ---------------------------------------------------------------------------
extern "C" void kernel_launch(void* const* d_in, const int* in_sizes, int n_in,
                              void* d_out, int out_size) {
    (void)in_sizes; (void)n_in; (void)out_size;
    const float* x = (const float*)d_in[0];
    const float* gamma = (const float*)d_in[1];
    float* out = (float*)d_out;

    const int smem1 = 8 * TILE_W * 4;   // 64 KB
    const int smem2 = 6 * TILE_W * 4;   // 48 KB
    cudaFuncSetAttribute(gemm1_h, cudaFuncAttributeMaxDynamicSharedMemorySize, smem1);
    cudaFuncSetAttribute(gemm2_h, cudaFuncAttributeMaxDynamicSharedMemorySize, smem2);

    transpose_h<<<dim3(Tn / 32, Cn / 32, Bn), dim3(32, 8)>>>(x);
    gemm1_h<<<dim3(Cn / 128, Cn / 128, Bn), 512, smem1>>>(x);
    softmax_kernel<<<Bn * Cn, 256>>>();
    gemm2_h<<<dim3(Tn / 128, Cn / 128, Bn), 512, smem2>>>(x, gamma, out);
}

// round 9
// speedup vs baseline: 1.5612x; 1.1188x over previous
#include <cuda_runtime.h>
#include <cuda_fp16.h>
#include <cstdint>

#define Bn 32
#define Cn 256
#define Tn 4096
#define TW 2048          // words per 128-row x 32-k f16 tile (128 x 16)
#define TWB 4096         // words per 256-row tile

// Static device scratch (allocation-guard legal).
__device__ float4   g_e4[(size_t)Bn * Cn * Cn / 4];      //  8 MB energy (fp32)
__device__ uint32_t g_ah32[(size_t)Bn * Cn * Cn / 2];    //  4 MB attn hi (f16)
__device__ uint32_t g_al32[(size_t)Bn * Cn * Cn / 2];    //  4 MB attn lo (f16)
__device__ uint32_t g_xth32[(size_t)Bn * Tn * Cn / 2];   // 67 MB X^T hi (f16)

// ---------------------------------------------------------------------------
__device__ __forceinline__ uint32_t packh2(__half a, __half b) {
    return (uint32_t)__half_as_ushort(a) | ((uint32_t)__half_as_ushort(b) << 16);
}
// Tile: rows x 16 words (word = f16 k-pair). Pair p -> quad (p>>3)*4+((p&3)^(row&3)),
// slot (p>>2)&1. Proven conflict-free for STS scalars + LDS.64 fragments (R8).
__device__ __forceinline__ int swz(int row, int p) {
    return row * 16 + (((p >> 3) << 2) + ((p & 3) ^ (row & 3))) * 2 + ((p >> 2) & 1);
}
__device__ __forceinline__ uint2 ldq(const uint32_t* t, int r, int ks, int tig) {
    return *(const uint2*)(t + r * 16 + (ks * 4 + (tig ^ (r & 3))) * 2);
}
__device__ __forceinline__ void mma_f16(float* d, const uint32_t* a, const uint32_t* b) {
    asm volatile(
        "mma.sync.aligned.m16n8k16.row.col.f32.f16.f16.f32 "
        "{%0,%1,%2,%3}, {%4,%5,%6,%7}, {%8,%9}, {%0,%1,%2,%3};"
        : "+f"(d[0]), "+f"(d[1]), "+f"(d[2]), "+f"(d[3])
        : "r"(a[0]), "r"(a[1]), "r"(a[2]), "r"(a[3]), "r"(b[0]), "r"(b[1]));
}

// ---------------------------------------------------------------------------
// GEMM1 fetch/stage (256 thr): fp32 source 128x32, split to f16 h+l tiles.
// ---------------------------------------------------------------------------
__device__ __forceinline__ void fetch1(const float* __restrict__ G, int ld,
                                       int k0, float4* v, int tid) {
#pragma unroll
    for (int it = 0; it < 4; it++) {
        int idx = it * 256 + tid, row = idx >> 3, q = idx & 7;
        v[it] = *(const float4*)(G + (size_t)row * ld + k0 + q * 4);
    }
}
__device__ __forceinline__ void stage1(uint32_t* __restrict__ H,
                                       uint32_t* __restrict__ L,
                                       const float4* v, int tid) {
#pragma unroll
    for (int it = 0; it < 4; it++) {
        int idx = it * 256 + tid, row = idx >> 3, q = idx & 7;
        float4 w = v[it];
        __half h0 = __float2half_rn(w.x), h1 = __float2half_rn(w.y);
        __half h2 = __float2half_rn(w.z), h3 = __float2half_rn(w.w);
        H[swz(row, 2 * q)]     = packh2(h0, h1);
        H[swz(row, 2 * q + 1)] = packh2(h2, h3);
        L[swz(row, 2 * q)]     = packh2(__float2half_rn(w.x - __half2float(h0)),
                                        __float2half_rn(w.y - __half2float(h1)));
        L[swz(row, 2 * q + 1)] = packh2(__float2half_rn(w.z - __half2float(h2)),
                                        __float2half_rn(w.w - __half2float(h3)));
    }
}

// ---------------------------------------------------------------------------
// GEMM1 chunk: warp tile 32x64 (2 m-atoms x 8 n-atoms), 3 products, BK=32.
// ---------------------------------------------------------------------------
__device__ __forceinline__ void chunk3(const uint32_t* sb, float acc[16][4],
                                       int warpM, int warpN, int gid, int tig) {
    const uint32_t *AH = sb, *AL = sb + TW, *BH = sb + 2 * TW, *BL = sb + 3 * TW;
#pragma unroll
    for (int ks = 0; ks < 2; ks++) {
        uint32_t ah[2][4], al[2][4], bh[8][2], bl[8][2];
#pragma unroll
        for (int ma = 0; ma < 2; ma++) {
            int r0 = warpM + ma * 16 + gid;
            uint2 u0 = ldq(AH, r0, ks, tig), u1 = ldq(AH, r0 + 8, ks, tig);
            ah[ma][0] = u0.x; ah[ma][1] = u1.x; ah[ma][2] = u0.y; ah[ma][3] = u1.y;
            uint2 v0 = ldq(AL, r0, ks, tig), v1 = ldq(AL, r0 + 8, ks, tig);
            al[ma][0] = v0.x; al[ma][1] = v1.x; al[ma][2] = v0.y; al[ma][3] = v1.y;
        }
#pragma unroll
        for (int na = 0; na < 8; na++) {
            int r = warpN + na * 8 + gid;
            uint2 u = ldq(BH, r, ks, tig); bh[na][0] = u.x; bh[na][1] = u.y;
            uint2 v = ldq(BL, r, ks, tig); bl[na][0] = v.x; bl[na][1] = v.y;
        }
#pragma unroll
        for (int ma = 0; ma < 2; ma++)
#pragma unroll
            for (int na = 0; na < 8; na++) {
                float* d = acc[ma * 8 + na];
                mma_f16(d, ah[ma], bh[na]);
                mma_f16(d, al[ma], bh[na]);
                mma_f16(d, ah[ma], bl[na]);
            }
    }
}
// GEMM2 chunk: warp tile 32x64, 2 products (A h+l, B hi), BK=32.
__device__ __forceinline__ void chunk2(const uint32_t* sb, float acc[16][4],
                                       int warpM, int warpN, int gid, int tig) {
    const uint32_t *AH = sb, *AL = sb + TW, *BH = sb + 2 * TW;
#pragma unroll
    for (int ks = 0; ks < 2; ks++) {
        uint32_t ah[2][4], al[2][4], bh[8][2];
#pragma unroll
        for (int ma = 0; ma < 2; ma++) {
            int r0 = warpM + ma * 16 + gid;
            uint2 u0 = ldq(AH, r0, ks, tig), u1 = ldq(AH, r0 + 8, ks, tig);
            ah[ma][0] = u0.x; ah[ma][1] = u1.x; ah[ma][2] = u0.y; ah[ma][3] = u1.y;
            uint2 v0 = ldq(AL, r0, ks, tig), v1 = ldq(AL, r0 + 8, ks, tig);
            al[ma][0] = v0.x; al[ma][1] = v1.x; al[ma][2] = v0.y; al[ma][3] = v1.y;
        }
#pragma unroll
        for (int na = 0; na < 8; na++) {
            int r = warpN + na * 8 + gid;
            uint2 u = ldq(BH, r, ks, tig); bh[na][0] = u.x; bh[na][1] = u.y;
        }
#pragma unroll
        for (int ma = 0; ma < 2; ma++)
#pragma unroll
            for (int na = 0; na < 8; na++) {
                float* d = acc[ma * 8 + na];
                mma_f16(d, ah[ma], bh[na]);
                mma_f16(d, al[ma], bh[na]);
            }
    }
}

// ---------------------------------------------------------------------------
// Transpose + f16-round: xt_h[b][t][c] = f16(x[b][c][t])  (proven R8 kernel)
// ---------------------------------------------------------------------------
__global__ __launch_bounds__(256) void transpose_h(const float* __restrict__ x) {
    __shared__ float tile[32][33];
    const int b = blockIdx.z, c0 = blockIdx.y * 32, t0 = blockIdx.x * 32;
    const int tx = threadIdx.x, ty = threadIdx.y;
    const float* Xb = x + ((size_t)b * Cn + c0) * Tn + t0;
    __half* Xt = (__half*)g_xth32 + ((size_t)b * Tn + t0) * Cn + c0;
#pragma unroll
    for (int r = 0; r < 32; r += 8) tile[ty + r][tx] = Xb[(size_t)(ty + r) * Tn + tx];
    __syncthreads();
#pragma unroll
    for (int r = 0; r < 32; r += 8)
        Xt[(size_t)(ty + r) * Cn + tx] = __float2half_rn(tile[tx][ty + r]);
}

// ---------------------------------------------------------------------------
// GEMM1: E[b] = X[b] * X[b]^T  (3xFP16).  grid (2,2,32), 256 thr, 64KB smem.
// ---------------------------------------------------------------------------
__global__ __launch_bounds__(256, 1) void gemm1_h(const float* __restrict__ x) {
    extern __shared__ uint32_t sm[];
    const int tid = threadIdx.x, lane = tid & 31, wid = tid >> 5;
    const int gid = lane >> 2, tig = lane & 3;
    const int warpM = (wid >> 1) * 32, warpN = (wid & 1) * 64;
    const float* Xb = x + (size_t)blockIdx.z * Cn * Tn;
    const float* Ag = Xb + (size_t)blockIdx.y * 128 * Tn;
    const float* Bg = Xb + (size_t)blockIdx.x * 128 * Tn;

    float acc[16][4];
#pragma unroll
    for (int a = 0; a < 16; a++)
#pragma unroll
        for (int c = 0; c < 4; c++) acc[a][c] = 0.f;

    float4 va[4], vb[4];
    fetch1(Ag, Tn, 0, va, tid);
    fetch1(Bg, Tn, 0, vb, tid);
    stage1(sm, sm + TW, va, tid);
    stage1(sm + 2 * TW, sm + 3 * TW, vb, tid);
    __syncthreads();

    const int NC = Tn / 32;
#pragma unroll 1
    for (int c = 0; c < NC; c++) {
        const int s = c & 1;
        if (c + 1 < NC) {
            fetch1(Ag, Tn, (c + 1) * 32, va, tid);
            fetch1(Bg, Tn, (c + 1) * 32, vb, tid);
        }
        chunk3(sm + s * 4 * TW, acc, warpM, warpN, gid, tig);
        if (c + 1 < NC) {
            uint32_t* nb = sm + (s ^ 1) * 4 * TW;
            stage1(nb, nb + TW, va, tid);
            stage1(nb + 2 * TW, nb + 3 * TW, vb, tid);
            __syncthreads();
        }
    }

    float* E = (float*)g_e4 + (size_t)blockIdx.z * Cn * Cn;
#pragma unroll
    for (int ma = 0; ma < 2; ma++)
#pragma unroll
        for (int na = 0; na < 8; na++) {
            const float* d = acc[ma * 8 + na];
            int r0 = blockIdx.y * 128 + warpM + ma * 16 + gid;
            int cc = blockIdx.x * 128 + warpN + na * 8 + 2 * tig;
            *(float2*)(E + (size_t)r0 * Cn + cc) = make_float2(d[0], d[1]);
            *(float2*)(E + (size_t)(r0 + 8) * Cn + cc) = make_float2(d[2], d[3]);
        }
}

// ---------------------------------------------------------------------------
// Softmax: w = exp(min_e - e)/sum; writes f16 hi+lo split of w.
// ---------------------------------------------------------------------------
__global__ __launch_bounds__(256) void softmax_kernel() {
    const int row = blockIdx.x;
    const float* E = (float*)g_e4 + (size_t)row * Cn;
    const int tid = threadIdx.x;

    float e = E[tid];
    float v = e;
#pragma unroll
    for (int o = 16; o; o >>= 1) v = fminf(v, __shfl_xor_sync(0xffffffffu, v, o));
    __shared__ float red[8];
    __shared__ float bc[2];
    if ((tid & 31) == 0) red[tid >> 5] = v;
    __syncthreads();
    if (tid == 0) {
        float m = red[0];
#pragma unroll
        for (int i = 1; i < 8; i++) m = fminf(m, red[i]);
        bc[0] = m;
    }
    __syncthreads();
    float p = expf(bc[0] - e);
    v = p;
#pragma unroll
    for (int o = 16; o; o >>= 1) v += __shfl_xor_sync(0xffffffffu, v, o);
    if ((tid & 31) == 0) red[tid >> 5] = v;
    __syncthreads();
    if (tid == 0) {
        float s = 0.f;
#pragma unroll
        for (int i = 0; i < 8; i++) s += red[i];
        bc[1] = 1.0f / s;
    }
    __syncthreads();
    float w = p * bc[1];
    __half h = __float2half_rn(w);
    ((__half*)g_ah32)[(size_t)row * Cn + tid] = h;
    ((__half*)g_al32)[(size_t)row * Cn + tid] =
        __float2half_rn(w - __half2float(h));
}

// ---------------------------------------------------------------------------
// GEMM2: out = gamma * (Attn * X) + X.  CTA 128x256, 16 warps (512 thr).
// A = attn h+l (pre-split), B = X^T hi.  grid (16,2,32) = 1024 blocks.
// ---------------------------------------------------------------------------
__global__ __launch_bounds__(512, 1) void gemm2_h(const float* __restrict__ x,
                                                  const float* __restrict__ gamma,
                                                  float* __restrict__ out) {
    extern __shared__ uint32_t sm[];   // per stage: Ah(2048) Al(2048) Bh(4096)
    const int tid = threadIdx.x, lane = tid & 31, wid = tid >> 5;
    const int gid = lane >> 2, tig = lane & 3;
    const int warpM = (wid >> 2) * 32, warpN = (wid & 3) * 64;
    const int bz = blockIdx.z, by = blockIdx.y, t0 = blockIdx.x * 256;

    const uint32_t* Ah = g_ah32 + ((size_t)bz * Cn + by * 128) * 128;
    const uint32_t* Al = g_al32 + ((size_t)bz * Cn + by * 128) * 128;
    const uint32_t* Bh = g_xth32 + ((size_t)bz * Tn + t0) * 128;

    float acc[16][4];
#pragma unroll
    for (int a = 0; a < 16; a++)
#pragma unroll
        for (int c = 0; c < 4; c++) acc[a][c] = 0.f;

    // Fetch maps: A tiles 2048 w -> 1 uint4/thread; B tile 4096 w -> 2 uint4.
    const int arow = tid >> 2, aq = tid & 3;
    uint4 vah, val, vbh[2];
    auto fetchA = [&](int cw) {
        vah = *(const uint4*)(Ah + (size_t)arow * 128 + cw + aq * 4);
        val = *(const uint4*)(Al + (size_t)arow * 128 + cw + aq * 4);
    };
    auto fetchB = [&](int cw) {
#pragma unroll
        for (int it = 0; it < 2; it++) {
            int idx = it * 512 + tid, row = idx >> 2, q = idx & 3;
            vbh[it] = *(const uint4*)(Bh + (size_t)row * 128 + cw + q * 4);
        }
    };
    auto stageAll = [&](uint32_t* st) {
        uint32_t* H = st;
        uint32_t* L = st + TW;
        H[swz(arow, 4 * aq)]     = vah.x; H[swz(arow, 4 * aq + 1)] = vah.y;
        H[swz(arow, 4 * aq + 2)] = vah.z; H[swz(arow, 4 * aq + 3)] = vah.w;
        L[swz(arow, 4 * aq)]     = val.x; L[swz(arow, 4 * aq + 1)] = val.y;
        L[swz(arow, 4 * aq + 2)] = val.z; L[swz(arow, 4 * aq + 3)] = val.w;
        uint32_t* B = st + 2 * TW;
#pragma unroll
        for (int it = 0; it < 2; it++) {
            int idx = it * 512 + tid, row = idx >> 2, q = idx & 3;
            B[swz(row, 4 * q)]     = vbh[it].x; B[swz(row, 4 * q + 1)] = vbh[it].y;
            B[swz(row, 4 * q + 2)] = vbh[it].z; B[swz(row, 4 * q + 3)] = vbh[it].w;
        }
    };

    fetchA(0);
    fetchB(0);
    stageAll(sm);
    __syncthreads();

    const int NC = Cn / 32;   // 8
#pragma unroll 1
    for (int c = 0; c < NC; c++) {
        const int s = c & 1;
        if (c + 1 < NC) {
            fetchA((c + 1) * 16);
            fetchB((c + 1) * 16);
        }
        chunk2(sm + s * (2 * TW + TWB), acc, warpM, warpN, gid, tig);
        if (c + 1 < NC) {
            stageAll(sm + (s ^ 1) * (2 * TW + TWB));
            __syncthreads();
        }
    }

    const float gm = __ldg(gamma);
    const float* Xb = x + (size_t)bz * Cn * Tn;
    float* Ob = out + (size_t)bz * Cn * Tn;
#pragma unroll
    for (int ma = 0; ma < 2; ma++)
#pragma unroll
        for (int na = 0; na < 8; na++) {
            const float* d = acc[ma * 8 + na];
            int r0 = by * 128 + warpM + ma * 16 + gid;
            int cc = t0 + warpN + na * 8 + 2 * tig;
            size_t o0 = (size_t)r0 * Tn + cc;
            size_t o1 = (size_t)(r0 + 8) * Tn + cc;
            float2 x0 = *(const float2*)(Xb + o0);
            float2 x1 = *(const float2*)(Xb + o1);
            *(float2*)(Ob + o0) = make_float2(gm * d[0] + x0.x, gm * d[1] + x0.y);
            *(float2*)(Ob + o1) = make_float2(gm * d[2] + x1.x, gm * d[3] + x1.y);
        }
}

// ---------------------------------------------------------------------------
extern "C" void kernel_launch(void* const* d_in, const int* in_sizes, int n_in,
                              void* d_out, int out_size) {
    (void)in_sizes; (void)n_in; (void)out_size;
    const float* x = (const float*)d_in[0];
    const float* gamma = (const float*)d_in[1];
    float* out = (float*)d_out;

    const int smem1 = 8 * TW * 4;                 // 64 KB (2 stages x 4 tiles)
    const int smem2 = 2 * (2 * TW + TWB) * 4;     // 64 KB (2 stages x Ah+Al+Bh)
    cudaFuncSetAttribute(gemm1_h, cudaFuncAttributeMaxDynamicSharedMemorySize, smem1);
    cudaFuncSetAttribute(gemm2_h, cudaFuncAttributeMaxDynamicSharedMemorySize, smem2);

    transpose_h<<<dim3(Tn / 32, Cn / 32, Bn), dim3(32, 8)>>>(x);
    gemm1_h<<<dim3(Cn / 128, Cn / 128, Bn), 256, smem1>>>(x);
    softmax_kernel<<<Bn * Cn, 256>>>();
    gemm2_h<<<dim3(Tn / 256, Cn / 128, Bn), 512, smem2>>>(x, gamma, out);
}